// round 13
// baseline (speedup 1.0000x reference)
#include <cuda_runtime.h>
#include <cuda_fp16.h>
#include <math.h>
#include <stdint.h>

#define N_NODES 500000
#define N_SEG   10000
#define M_PAD   10112            // 79 * 128
#define DIM     256
#define NGATE   1024
#define QSTAR   512
#define NITER   6
#define NCTA    632              // 79 * 8 tiles per GEMM unit
#define PARTSZ  ((size_t)NCTA * 128 * 32)   // float4s per partial layer

// ---------------- scratch (device globals) -----------------------------------
__device__ half   g_featsh[(size_t)N_NODES * DIM];           // fp16 feats copy
__device__ half   g_qstar[(size_t)M_PAD * 512];              // fp16 [q|r]
__device__ half   g_hh[2 * 3 * (size_t)M_PAD * 256];          // fp16 h ping-pong x 3
__device__ float  g_c[3 * (size_t)M_PAD * DIM];
__device__ float  g_hq[(size_t)M_PAD * DIM];                  // fp32 q for attn
__device__ half   g_w_ih[3][(size_t)NGATE * 512];
__device__ half   g_w_hh[3][(size_t)NGATE * 256];
__device__ float  g_bp[3 * NGATE];
__device__ float4 g_part[2 * PARTSZ];                         // hh partial gates, 83 MB
__device__ int    g_start[N_SEG + 1];

// ---------------- helpers ------------------------------------------------------
__device__ __forceinline__ uint32_t smem_u32(const void* p) {
    return (uint32_t)__cvta_generic_to_shared(p);
}
__device__ __forceinline__ void cp16(uint32_t dst, const void* src) {
    asm volatile("cp.async.cg.shared.global [%0], [%1], 16;" :: "r"(dst), "l"(src));
}
#define CP_COMMIT() asm volatile("cp.async.commit_group;" ::: "memory")
#define CP_WAIT(n)  asm volatile("cp.async.wait_group %0;" :: "n"(n) : "memory")

__device__ __forceinline__ void ldsm_x4(uint32_t& r0, uint32_t& r1, uint32_t& r2, uint32_t& r3,
                                        uint32_t addr) {
    asm volatile("ldmatrix.sync.aligned.m8n8.x4.shared.b16 {%0,%1,%2,%3}, [%4];"
        : "=r"(r0), "=r"(r1), "=r"(r2), "=r"(r3) : "r"(addr));
}
__device__ __forceinline__ void mma_f16(float4& d, const uint32_t* a, uint32_t b0, uint32_t b1) {
    asm volatile(
        "mma.sync.aligned.m16n8k16.row.col.f32.f16.f16.f32 "
        "{%0,%1,%2,%3}, {%4,%5,%6,%7}, {%8,%9}, {%0,%1,%2,%3};"
        : "+f"(d.x), "+f"(d.y), "+f"(d.z), "+f"(d.w)
        : "r"(a[0]), "r"(a[1]), "r"(a[2]), "r"(a[3]), "r"(b0), "r"(b1));
}

__device__ __forceinline__ float sigf(float x) { return 1.0f / (1.0f + __expf(-x)); }
__device__ __forceinline__ float tanhfast(float x) { return 2.0f / (1.0f + __expf(-2.0f * x)) - 1.0f; }

// ---------------- fragment addressing: 4 warps (2x2), warp tile 64x64 ----------
struct Frag {
    uint32_t a_base[4], a_xc[4], b_base[4], b_xc[4];
};
__device__ __forceinline__ Frag make_frag(uint32_t sbase, int wid, int lane, uint32_t b_off) {
    Frag f;
    const int warp_m = wid & 1;
    const int warp_n = wid >> 1;
    const int koff = (lane >> 4) * 16;
#pragma unroll
    for (int tm = 0; tm < 4; tm++) {
        int row = warp_m * 64 + tm * 16 + (lane & 15);
        f.a_base[tm] = sbase + row * 128;
        f.a_xc[tm] = (uint32_t)(koff ^ ((row & 7) << 4));
    }
#pragma unroll
    for (int tn2 = 0; tn2 < 4; tn2++) {
        int row = warp_n * 64 + tn2 * 16 + (lane & 15);
        f.b_base[tn2] = sbase + b_off + row * 128;
        f.b_xc[tn2] = (uint32_t)(koff ^ ((row & 7) << 4));
    }
    return f;
}

// one chunk: 4 ks-steps; per ks 4 a-ldsm + 4 b-ldsm -> 32 mma
__device__ __forceinline__ void consume_chunk(const Frag& f, uint32_t stoff, float4 (&acc)[4][8]) {
#pragma unroll
    for (int ks = 0; ks < 4; ks++) {
        uint32_t a[4][4];
#pragma unroll
        for (int tm = 0; tm < 4; tm++)
            ldsm_x4(a[tm][0], a[tm][1], a[tm][2], a[tm][3],
                    f.a_base[tm] + stoff + ((uint32_t)(ks * 32) ^ f.a_xc[tm]));
        uint32_t b[4][4];
#pragma unroll
        for (int tn2 = 0; tn2 < 4; tn2++)
            ldsm_x4(b[tn2][0], b[tn2][1], b[tn2][2], b[tn2][3],
                    f.b_base[tn2] + stoff + ((uint32_t)(ks * 32) ^ f.b_xc[tn2]));
#pragma unroll
        for (int tm = 0; tm < 4; tm++)
#pragma unroll
            for (int tn2 = 0; tn2 < 4; tn2++) {
                mma_f16(acc[tm][tn2 * 2 + 0], a[tm], b[tn2][0], b[tn2][2]);
                mma_f16(acc[tm][tn2 * 2 + 1], a[tm], b[tn2][1], b[tn2][3]);
            }
    }
}

// fused LSTM epilogue (4-warp layout)
__device__ __forceinline__ void lstm_epilogue(float4 (&acc)[4][8], int lane, int wid,
                                              int bm, int bn, const float* bias,
                                              float* c, half* hout, float* hq, int write_q) {
    const int warp_m = wid & 1;
    const int warp_n = wid >> 1;
    const bool even = !(lane & 1);
#pragma unroll
    for (int tm = 0; tm < 4; tm++) {
#pragma unroll
        for (int tn = 0; tn < 8; tn++) {
            float4 d = acc[tm][tn];
            float e0 = __shfl_xor_sync(0xffffffffu, d.x, 1);
            float e1 = __shfl_xor_sync(0xffffffffu, d.y, 1);
            float e2 = __shfl_xor_sync(0xffffffffu, d.z, 1);
            float e3 = __shfl_xor_sync(0xffffffffu, d.w, 1);
            if (even) {
                int col = bn + warp_n * 64 + tn * 8 + (lane & 3) * 2;
                int u = col >> 2;
                float4 bi = *(const float4*)&bias[col];
                int rA = bm + warp_m * 64 + tm * 16 + (lane >> 2);
#pragma unroll
                for (int rh = 0; rh < 2; rh++) {
                    int row = rA + rh * 8;
                    float gi = (rh ? d.z : d.x) + bi.x;
                    float gf = (rh ? d.w : d.y) + bi.y;
                    float gg = (rh ? e2 : e0) + bi.z;
                    float go = (rh ? e3 : e1) + bi.w;
                    size_t cidx = (size_t)row * DIM + u;
                    float cn = sigf(gf) * c[cidx] + sigf(gi) * tanhfast(gg);
                    c[cidx] = cn;
                    float hn = sigf(go) * tanhfast(cn);
                    hout[(size_t)row * 256 + u] = __float2half_rn(hn);
                    if (write_q) hq[(size_t)row * DIM + u] = hn;
                }
            }
        }
    }
}

// ---------------- prep / conv / init --------------------------------------------
struct PermArgs {
    const float* w_ih[3]; const float* w_hh[3];
    const float* b_ih[3]; const float* b_hh[3];
    int K1[3];
};
__global__ void prep_kernel(PermArgs pa) {
    int l = blockIdx.y;
    int K1 = pa.K1[l];
    half* wih = g_w_ih[l];
    half* whh = g_w_hh[l];
    int n_ih = NGATE * K1, n_hh = NGATE * DIM;
    int total = n_ih + n_hh + NGATE;
    for (int i = blockIdx.x * blockDim.x + threadIdx.x; i < total; i += gridDim.x * blockDim.x) {
        if (i < n_ih) {
            int r = i / K1, k = i - r * K1;
            int u = r >> 2, g = r & 3;
            wih[i] = __float2half_rn(pa.w_ih[l][(size_t)(g * 256 + u) * K1 + k]);
        } else if (i < n_ih + n_hh) {
            int j = i - n_ih;
            int r = j / DIM, k = j - r * DIM;
            int u = r >> 2, g = r & 3;
            whh[j] = __float2half_rn(pa.w_hh[l][(size_t)(g * 256 + u) * DIM + k]);
        } else {
            int r = i - n_ih - n_hh;
            int u = r >> 2, g = r & 3;
            g_bp[l * NGATE + r] = pa.b_ih[l][g * 256 + u] + pa.b_hh[l][g * 256 + u];
        }
    }
}

__global__ void feats_conv_kernel(const float* __restrict__ feats) {
    size_t i = ((size_t)blockIdx.x * blockDim.x + threadIdx.x) * 4;
    size_t stride = (size_t)gridDim.x * blockDim.x * 4;
    const size_t n = (size_t)N_NODES * DIM;
    for (; i < n; i += stride) {
        float4 v = *(const float4*)(feats + i);
        half2 h0 = __floats2half2_rn(v.x, v.y);
        half2 h1 = __floats2half2_rn(v.z, v.w);
        *(uint2*)(g_featsh + i) = make_uint2(*(uint32_t*)&h0, *(uint32_t*)&h1);
    }
}

__global__ void init_kernel(const int* __restrict__ seg) {
    size_t gid = (size_t)blockIdx.x * blockDim.x + threadIdx.x;
    size_t stride = (size_t)gridDim.x * blockDim.x;
    const size_t nq = (size_t)M_PAD * 512;
    const size_t nh = (size_t)2 * 3 * M_PAD * 256;
    const size_t nc = (size_t)3 * M_PAD * DIM;
    half z = __float2half_rn(0.0f);
    for (size_t i = gid; i < nq; i += stride) g_qstar[i] = z;
    for (size_t i = gid; i < nh; i += stride) g_hh[i] = z;
    for (size_t i = gid; i < nc; i += stride) g_c[i] = 0.0f;
    if (gid <= N_SEG) {
        int s = (int)gid;
        int lo = 0, hi = N_NODES;
        while (lo < hi) { int mid = (lo + hi) >> 1; if (seg[mid] < s) lo = mid + 1; else hi = mid; }
        g_start[s] = lo;
    }
}

// ---------------- pipeline constants --------------------------------------------
#define SM_BUF   16384
#define STAGE_SZ 32768
#define SMEM_GE  (3 * STAGE_SZ)

// ---------------- launch A: l0 full GEMM+LSTM  |  l1/l2 hh partials -------------
__global__ __launch_bounds__(128, 2)
void gemmA(const half* __restrict__ qs, const half* __restrict__ wih0,
           const half* __restrict__ h0p, const half* __restrict__ whh0,
           const float* __restrict__ bias0, float* __restrict__ c0,
           half* __restrict__ h0out,
           const half* __restrict__ h1p, const half* __restrict__ whh1,
           const half* __restrict__ h2p, const half* __restrict__ whh2) {
    extern __shared__ __align__(128) char smem[];
    const uint32_t sbase = smem_u32(smem);
    const int tid = threadIdx.x;
    const int lane = tid & 31;
    const int wid = tid >> 5;
    const int bm = blockIdx.x * 128;
    const int bn = blockIdx.y * 128;
    const int z = blockIdx.z;

    const int r0 = tid >> 3;          // 0..15
    const int sg = tid & 7;
    const uint32_t so0 = (uint32_t)(r0 * 128 + ((sg * 16) ^ ((r0 & 7) << 4)));

    float4 acc[4][8];
#pragma unroll
    for (int i = 0; i < 4; i++)
#pragma unroll
        for (int j = 0; j < 8; j++) acc[i][j] = make_float4(0.f, 0.f, 0.f, 0.f);

    Frag frag = make_frag(sbase, wid, lane, SM_BUF);

    if (z == 0) {
        constexpr int C1 = 8, NC = 12;
        const half* a1p = qs + (size_t)(bm + r0) * 512 + sg * 8;
        const half* w1p = wih0 + (size_t)(bn + r0) * 512 + sg * 8;
        const half* a2p = h0p + (size_t)(bm + r0) * 256 + sg * 8;
        const half* w2p = whh0 + (size_t)(bn + r0) * 256 + sg * 8;

        auto load_chunk = [&](int g, int st) {
            const uint32_t sA = sbase + st * STAGE_SZ + so0;
            const uint32_t sB = sA + SM_BUF;
            if (g < C1) {
                const int off = g * 64;
#pragma unroll
                for (int q = 0; q < 8; q++) {
                    constexpr size_t ST = (size_t)16 * 512;
                    cp16(sA + q * 2048, a1p + q * ST + off);
                    cp16(sB + q * 2048, w1p + q * ST + off);
                }
            } else {
                const int off = (g - C1) * 64;
#pragma unroll
                for (int q = 0; q < 8; q++) {
                    constexpr size_t ST = (size_t)16 * 256;
                    cp16(sA + q * 2048, a2p + q * ST + off);
                    cp16(sB + q * 2048, w2p + q * ST + off);
                }
            }
            CP_COMMIT();
        };

        load_chunk(0, 0);
        load_chunk(1, 1);
        int st_cur = 0, st_nxt = 2;
#pragma unroll 1
        for (int g = 0; g < NC; g++) {
            if (g + 1 < NC) { CP_WAIT(1); } else { CP_WAIT(0); }
            __syncthreads();
            if (g + 2 < NC) load_chunk(g + 2, st_nxt);
            consume_chunk(frag, st_cur * STAGE_SZ, acc);
            st_cur = (st_cur == 2) ? 0 : st_cur + 1;
            st_nxt = (st_nxt == 2) ? 0 : st_nxt + 1;
        }
        lstm_epilogue(acc, lane, wid, bm, bn, bias0, c0, h0out, (float*)0, 0);
    } else {
        const half* A = (z == 1) ? h1p : h2p;
        const half* W = (z == 1) ? whh1 : whh2;
        const half* ap = A + (size_t)(bm + r0) * 256 + sg * 8;
        const half* wp = W + (size_t)(bn + r0) * 256 + sg * 8;

        auto load_chunk = [&](int g, int st) {
            const uint32_t sA = sbase + st * STAGE_SZ + so0;
            const uint32_t sB = sA + SM_BUF;
            const int off = g * 64;
#pragma unroll
            for (int q = 0; q < 8; q++) {
                constexpr size_t ST = (size_t)16 * 256;
                cp16(sA + q * 2048, ap + q * ST + off);
                cp16(sB + q * 2048, wp + q * ST + off);
            }
            CP_COMMIT();
        };

        load_chunk(0, 0);
        load_chunk(1, 1);
        int st_cur = 0, st_nxt = 2;
#pragma unroll 1
        for (int g = 0; g < 4; g++) {
            if (g + 1 < 4) { CP_WAIT(1); } else { CP_WAIT(0); }
            __syncthreads();
            if (g + 2 < 4) load_chunk(g + 2, st_nxt);
            consume_chunk(frag, st_cur * STAGE_SZ, acc);
            st_cur = (st_cur == 2) ? 0 : st_cur + 1;
            st_nxt = (st_nxt == 2) ? 0 : st_nxt + 1;
        }
        const size_t cta = (size_t)(z - 1) * NCTA + blockIdx.x * 8 + blockIdx.y;
        float4* pp = g_part + cta * (32 * 128) + tid;
#pragma unroll
        for (int i = 0; i < 4; i++)
#pragma unroll
            for (int j = 0; j < 8; j++) pp[(i * 8 + j) * 128] = acc[i][j];
    }
}

// ---------------- finish: ih GEMM (NC=4) + partial add + LSTM -------------------
__global__ __launch_bounds__(128, 2)
void gemmF(const half* __restrict__ A1, const half* __restrict__ W1,
           const float* __restrict__ bias, const float4* __restrict__ gpart,
           float* __restrict__ c, half* __restrict__ hout,
           float* __restrict__ hq, int write_q) {
    extern __shared__ __align__(128) char smem[];
    const uint32_t sbase = smem_u32(smem);
    const int tid = threadIdx.x;
    const int lane = tid & 31;
    const int wid = tid >> 5;
    const int bm = blockIdx.x * 128;
    const int bn = blockIdx.y * 128;

    const int r0 = tid >> 3;
    const int sg = tid & 7;
    const uint32_t so0 = (uint32_t)(r0 * 128 + ((sg * 16) ^ ((r0 & 7) << 4)));
    const half* ap = A1 + (size_t)(bm + r0) * 256 + sg * 8;
    const half* wp = W1 + (size_t)(bn + r0) * 256 + sg * 8;

    auto load_chunk = [&](int g, int st) {
        const uint32_t sA = sbase + st * STAGE_SZ + so0;
        const uint32_t sB = sA + SM_BUF;
        const int off = g * 64;
#pragma unroll
        for (int q = 0; q < 8; q++) {
            constexpr size_t ST = (size_t)16 * 256;
            cp16(sA + q * 2048, ap + q * ST + off);
            cp16(sB + q * 2048, wp + q * ST + off);
        }
        CP_COMMIT();
    };

    float4 acc[4][8];
#pragma unroll
    for (int i = 0; i < 4; i++)
#pragma unroll
        for (int j = 0; j < 8; j++) acc[i][j] = make_float4(0.f, 0.f, 0.f, 0.f);

    Frag frag = make_frag(sbase, wid, lane, SM_BUF);

    load_chunk(0, 0);
    load_chunk(1, 1);
    int st_cur = 0, st_nxt = 2;
#pragma unroll 1
    for (int g = 0; g < 4; g++) {
        if (g + 1 < 4) { CP_WAIT(1); } else { CP_WAIT(0); }
        __syncthreads();
        if (g + 2 < 4) load_chunk(g + 2, st_nxt);
        consume_chunk(frag, st_cur * STAGE_SZ, acc);
        st_cur = (st_cur == 2) ? 0 : st_cur + 1;
        st_nxt = (st_nxt == 2) ? 0 : st_nxt + 1;
    }

    const size_t cta = (size_t)blockIdx.x * 8 + blockIdx.y;
    const float4* pp = gpart + cta * (32 * 128) + tid;
#pragma unroll
    for (int i = 0; i < 4; i++)
#pragma unroll
        for (int j = 0; j < 8; j++) {
            float4 p = pp[(i * 8 + j) * 128];
            acc[i][j].x += p.x; acc[i][j].y += p.y;
            acc[i][j].z += p.z; acc[i][j].w += p.w;
        }

    lstm_epilogue(acc, lane, wid, bm, bn, bias, c, hout, hq, write_q);
}

// ---------------- fused attention (unchanged) ------------------------------------
__global__ void attn_kernel(const float* __restrict__ q, float* __restrict__ out) {
    const int s = blockIdx.x;
    const int lo = g_start[s], hi = g_start[s + 1];
    const int w = threadIdx.x >> 5;
    const int lane = threadIdx.x & 31;

    __shared__ float sm_m[8];
    __shared__ float sm_s[8];
    __shared__ float sm_r[8][256];

    float qf[8];
    *(float4*)&qf[0] = *(const float4*)(q + (size_t)s * DIM + lane * 8);
    *(float4*)&qf[4] = *(const float4*)(q + (size_t)s * DIM + lane * 8 + 4);

    float m = -INFINITY, ssum = 0.0f;
    float r[8];
#pragma unroll
    for (int j = 0; j < 8; j++) r[j] = 0.0f;

    for (int n = lo + w; n < hi; n += 8) {
        uint4 fv = *(const uint4*)(g_featsh + (size_t)n * DIM + lane * 8);
        float2 f0 = __half22float2(*(half2*)&fv.x);
        float2 f1 = __half22float2(*(half2*)&fv.y);
        float2 f2 = __half22float2(*(half2*)&fv.z);
        float2 f3 = __half22float2(*(half2*)&fv.w);
        float ff[8] = {f0.x, f0.y, f1.x, f1.y, f2.x, f2.y, f3.x, f3.y};
        float d = 0.0f;
#pragma unroll
        for (int j = 0; j < 8; j++) d = fmaf(ff[j], qf[j], d);
#pragma unroll
        for (int o = 16; o > 0; o >>= 1) d += __shfl_xor_sync(0xffffffffu, d, o);

        float mn = fmaxf(m, d);
        float sc = __expf(m - mn);
        float p  = __expf(d - mn);
        ssum = ssum * sc + p;
#pragma unroll
        for (int j = 0; j < 8; j++) r[j] = r[j] * sc + p * ff[j];
        m = mn;
    }

    if (lane == 0) { sm_m[w] = m; sm_s[w] = ssum; }
    *(float4*)&sm_r[w][lane * 8]     = *(float4*)&r[0];
    *(float4*)&sm_r[w][lane * 8 + 4] = *(float4*)&r[4];
    __syncthreads();

    const int t = threadIdx.x;
    float M = -INFINITY;
#pragma unroll
    for (int k = 0; k < 8; k++)
        if (sm_s[k] > 0.0f) M = fmaxf(M, sm_m[k]);
    float S = 0.0f, R = 0.0f;
#pragma unroll
    for (int k = 0; k < 8; k++) {
        if (sm_s[k] > 0.0f) {
            float sc = __expf(sm_m[k] - M);
            S += sm_s[k] * sc;
            R += sm_r[k][t] * sc;
        }
    }
    float rv = (S > 0.0f) ? R / S : 0.0f;
    float qv_ = q[(size_t)s * DIM + t];
    out[(size_t)s * QSTAR + t]       = qv_;
    out[(size_t)s * QSTAR + DIM + t] = rv;

    half* qs = g_qstar + (size_t)s * 512;
    qs[t]       = __float2half_rn(qv_);
    qs[256 + t] = __float2half_rn(rv);
}

// ---------------- host orchestration -------------------------------------------
extern "C" void kernel_launch(void* const* d_in, const int* in_sizes, int n_in,
                              void* d_out, int out_size) {
    const float* feats = (const float*)d_in[0];
    const int* seg = (const int*)d_in[1];
    float* out = (float*)d_out;

    PermArgs pa;
    for (int l = 0; l < 3; l++) {
        pa.w_ih[l] = (const float*)d_in[2 + 4 * l];
        pa.w_hh[l] = (const float*)d_in[3 + 4 * l];
        pa.b_ih[l] = (const float*)d_in[4 + 4 * l];
        pa.b_hh[l] = (const float*)d_in[5 + 4 * l];
        pa.K1[l] = (l == 0) ? QSTAR : DIM;
    }

    half *qs, *hh; float *c, *hq, *bp; half *wih[3], *whh[3]; float4* gpart;
    cudaGetSymbolAddress((void**)&qs, g_qstar);
    cudaGetSymbolAddress((void**)&hh, g_hh);
    cudaGetSymbolAddress((void**)&c, g_c);
    cudaGetSymbolAddress((void**)&hq, g_hq);
    cudaGetSymbolAddress((void**)&bp, g_bp);
    cudaGetSymbolAddress((void**)&gpart, g_part);
    {
        half* base_ih; half* base_hh;
        cudaGetSymbolAddress((void**)&base_ih, g_w_ih);
        cudaGetSymbolAddress((void**)&base_hh, g_w_hh);
        for (int l = 0; l < 3; l++) {
            wih[l] = base_ih + (size_t)l * NGATE * 512;
            whh[l] = base_hh + (size_t)l * NGATE * 256;
        }
    }

    cudaFuncSetAttribute(gemmA, cudaFuncAttributeMaxDynamicSharedMemorySize, SMEM_GE);
    cudaFuncSetAttribute(gemmF, cudaFuncAttributeMaxDynamicSharedMemorySize, SMEM_GE);

    dim3 pgrid(256, 3);
    prep_kernel<<<pgrid, 256>>>(pa);
    feats_conv_kernel<<<2048, 256>>>(feats);
    init_kernel<<<1184, 256>>>(seg);

    const size_t SDH = (size_t)M_PAD * 256;
    dim3 gA(M_PAD / 128, NGATE / 128, 3);
    dim3 gF(M_PAD / 128, NGATE / 128);

    for (int it = 0; it < NITER; it++) {
        half* hin  = hh + (size_t)(it & 1) * 3 * SDH;
        half* hout = hh + (size_t)((it + 1) & 1) * 3 * SDH;

        gemmA<<<gA, 128, SMEM_GE>>>(qs, wih[0], hin, whh[0], bp, c, hout,
                                    hin + 1 * SDH, whh[1],
                                    hin + 2 * SDH, whh[2]);
        gemmF<<<gF, 128, SMEM_GE>>>(hout, wih[1], bp + NGATE, gpart,
                                    c + 1 * (size_t)M_PAD * DIM, hout + 1 * SDH, hq, 0);
        gemmF<<<gF, 128, SMEM_GE>>>(hout + 1 * SDH, wih[2], bp + 2 * NGATE, gpart + PARTSZ,
                                    c + 2 * (size_t)M_PAD * DIM, hout + 2 * SDH, hq, 1);
        attn_kernel<<<N_SEG, 256>>>(hq, out);
    }
}

// round 14
// speedup vs baseline: 1.5759x; 1.5759x over previous
#include <cuda_runtime.h>
#include <cuda_fp16.h>
#include <math.h>
#include <stdint.h>

#define N_NODES 500000
#define N_SEG   10000
#define M_PAD   10112            // 79 * 128
#define DIM     256
#define NGATE   1024
#define QSTAR   512
#define NITER   6
#define NCTA    632              // 79 * 8 tiles per GEMM unit
#define PARTSZ  ((size_t)NCTA * 256 * 16)   // float4s per partial layer

// ---------------- scratch (device globals) -----------------------------------
__device__ half   g_featsh[(size_t)N_NODES * DIM];           // fp16 feats copy
__device__ half   g_qstar[(size_t)M_PAD * 512];              // fp16 [q|r]
__device__ half   g_hh[2 * 3 * (size_t)M_PAD * 256];          // fp16 h ping-pong x 3
__device__ float  g_c[3 * (size_t)M_PAD * DIM];
__device__ float  g_hq[(size_t)M_PAD * DIM];                  // fp32 q for attn
__device__ half   g_w_ih[3][(size_t)NGATE * 512];
__device__ half   g_w_hh[3][(size_t)NGATE * 256];
__device__ float  g_bp[3 * NGATE];
__device__ float4 g_part[2 * PARTSZ];                         // hh partial gates, 83 MB
__device__ int    g_start[N_SEG + 1];

// ---------------- helpers ------------------------------------------------------
__device__ __forceinline__ uint32_t smem_u32(const void* p) {
    return (uint32_t)__cvta_generic_to_shared(p);
}
__device__ __forceinline__ void cp16(uint32_t dst, const void* src) {
    asm volatile("cp.async.cg.shared.global [%0], [%1], 16;" :: "r"(dst), "l"(src));
}
#define CP_COMMIT() asm volatile("cp.async.commit_group;" ::: "memory")
#define CP_WAIT(n)  asm volatile("cp.async.wait_group %0;" :: "n"(n) : "memory")

__device__ __forceinline__ void ldsm_x4(uint32_t& r0, uint32_t& r1, uint32_t& r2, uint32_t& r3,
                                        uint32_t addr) {
    asm volatile("ldmatrix.sync.aligned.m8n8.x4.shared.b16 {%0,%1,%2,%3}, [%4];"
        : "=r"(r0), "=r"(r1), "=r"(r2), "=r"(r3) : "r"(addr));
}
__device__ __forceinline__ void mma_f16(float4& d, const uint32_t* a, uint32_t b0, uint32_t b1) {
    asm volatile(
        "mma.sync.aligned.m16n8k16.row.col.f32.f16.f16.f32 "
        "{%0,%1,%2,%3}, {%4,%5,%6,%7}, {%8,%9}, {%0,%1,%2,%3};"
        : "+f"(d.x), "+f"(d.y), "+f"(d.z), "+f"(d.w)
        : "r"(a[0]), "r"(a[1]), "r"(a[2]), "r"(a[3]), "r"(b0), "r"(b1));
}

__device__ __forceinline__ float sigf(float x) { return 1.0f / (1.0f + __expf(-x)); }
__device__ __forceinline__ float tanhfast(float x) { return 2.0f / (1.0f + __expf(-2.0f * x)) - 1.0f; }

// shared fragment-address setup (8 warps: 4 M x 2 N, warp tile 32x64)
struct Frag {
    uint32_t a_base[2], a_xc[2], b_base[4], b_xc[4];
};
__device__ __forceinline__ Frag make_frag(uint32_t sbase, int wid, int lane, uint32_t b_off) {
    Frag f;
    const int warp_m = wid & 3;
    const int warp_n = wid >> 2;
    const int koff = (lane >> 4) * 16;
#pragma unroll
    for (int tm = 0; tm < 2; tm++) {
        int row = warp_m * 32 + tm * 16 + (lane & 15);
        f.a_base[tm] = sbase + row * 128;
        f.a_xc[tm] = (uint32_t)(koff ^ ((row & 7) << 4));
    }
#pragma unroll
    for (int tn2 = 0; tn2 < 4; tn2++) {
        int row = warp_n * 64 + tn2 * 16 + (lane & 15);
        f.b_base[tn2] = sbase + b_off + row * 128;
        f.b_xc[tn2] = (uint32_t)(koff ^ ((row & 7) << 4));
    }
    return f;
}

// one chunk of compute: 4 ks-steps of ldsm+mma from stage offset
__device__ __forceinline__ void consume_chunk(const Frag& f, uint32_t stoff, float4 (&acc)[2][8]) {
#pragma unroll
    for (int ks = 0; ks < 4; ks++) {
        uint32_t a[2][4];
#pragma unroll
        for (int tm = 0; tm < 2; tm++)
            ldsm_x4(a[tm][0], a[tm][1], a[tm][2], a[tm][3],
                    f.a_base[tm] + stoff + ((uint32_t)(ks * 32) ^ f.a_xc[tm]));
        uint32_t b[4][4];
#pragma unroll
        for (int tn2 = 0; tn2 < 4; tn2++)
            ldsm_x4(b[tn2][0], b[tn2][1], b[tn2][2], b[tn2][3],
                    f.b_base[tn2] + stoff + ((uint32_t)(ks * 32) ^ f.b_xc[tn2]));
#pragma unroll
        for (int tm = 0; tm < 2; tm++)
#pragma unroll
            for (int tn2 = 0; tn2 < 4; tn2++) {
                mma_f16(acc[tm][tn2 * 2 + 0], a[tm], b[tn2][0], b[tn2][2]);
                mma_f16(acc[tm][tn2 * 2 + 1], a[tm], b[tn2][1], b[tn2][3]);
            }
    }
}

// fused LSTM epilogue
__device__ __forceinline__ void lstm_epilogue(float4 (&acc)[2][8], int lane, int wid,
                                              int bm, int bn, const float* bias,
                                              float* c, half* hout, float* hq, int write_q) {
    const int warp_m = wid & 3;
    const int warp_n = wid >> 2;
    const bool even = !(lane & 1);
#pragma unroll
    for (int tm = 0; tm < 2; tm++) {
#pragma unroll
        for (int tn = 0; tn < 8; tn++) {
            float4 d = acc[tm][tn];
            float e0 = __shfl_xor_sync(0xffffffffu, d.x, 1);
            float e1 = __shfl_xor_sync(0xffffffffu, d.y, 1);
            float e2 = __shfl_xor_sync(0xffffffffu, d.z, 1);
            float e3 = __shfl_xor_sync(0xffffffffu, d.w, 1);
            if (even) {
                int col = bn + warp_n * 64 + tn * 8 + (lane & 3) * 2;
                int u = col >> 2;
                float4 bi = *(const float4*)&bias[col];
                int rA = bm + warp_m * 32 + tm * 16 + (lane >> 2);
#pragma unroll
                for (int rh = 0; rh < 2; rh++) {
                    int row = rA + rh * 8;
                    float gi = (rh ? d.z : d.x) + bi.x;
                    float gf = (rh ? d.w : d.y) + bi.y;
                    float gg = (rh ? e2 : e0) + bi.z;
                    float go = (rh ? e3 : e1) + bi.w;
                    size_t cidx = (size_t)row * DIM + u;
                    float cn = sigf(gf) * c[cidx] + sigf(gi) * tanhfast(gg);
                    c[cidx] = cn;
                    float hn = sigf(go) * tanhfast(cn);
                    hout[(size_t)row * 256 + u] = __float2half_rn(hn);
                    if (write_q) hq[(size_t)row * DIM + u] = hn;
                }
            }
        }
    }
}

// ---------------- prep / conv / init ----------------------------------------------
struct PermArgs {
    const float* w_ih[3]; const float* w_hh[3];
    const float* b_ih[3]; const float* b_hh[3];
    int K1[3];
};
__global__ void prep_kernel(PermArgs pa) {
    int l = blockIdx.y;
    int K1 = pa.K1[l];
    half* wih = g_w_ih[l];
    half* whh = g_w_hh[l];
    int n_ih = NGATE * K1, n_hh = NGATE * DIM;
    int total = n_ih + n_hh + NGATE;
    for (int i = blockIdx.x * blockDim.x + threadIdx.x; i < total; i += gridDim.x * blockDim.x) {
        if (i < n_ih) {
            int r = i / K1, k = i - r * K1;
            int u = r >> 2, g = r & 3;
            wih[i] = __float2half_rn(pa.w_ih[l][(size_t)(g * 256 + u) * K1 + k]);
        } else if (i < n_ih + n_hh) {
            int j = i - n_ih;
            int r = j / DIM, k = j - r * DIM;
            int u = r >> 2, g = r & 3;
            whh[j] = __float2half_rn(pa.w_hh[l][(size_t)(g * 256 + u) * DIM + k]);
        } else {
            int r = i - n_ih - n_hh;
            int u = r >> 2, g = r & 3;
            g_bp[l * NGATE + r] = pa.b_ih[l][g * 256 + u] + pa.b_hh[l][g * 256 + u];
        }
    }
}

__global__ void feats_conv_kernel(const float* __restrict__ feats) {
    size_t i = ((size_t)blockIdx.x * blockDim.x + threadIdx.x) * 4;
    size_t stride = (size_t)gridDim.x * blockDim.x * 4;
    const size_t n = (size_t)N_NODES * DIM;
    for (; i < n; i += stride) {
        float4 v = *(const float4*)(feats + i);
        half2 h0 = __floats2half2_rn(v.x, v.y);
        half2 h1 = __floats2half2_rn(v.z, v.w);
        *(uint2*)(g_featsh + i) = make_uint2(*(uint32_t*)&h0, *(uint32_t*)&h1);
    }
}

__global__ void init_kernel(const int* __restrict__ seg) {
    size_t gid = (size_t)blockIdx.x * blockDim.x + threadIdx.x;
    size_t stride = (size_t)gridDim.x * blockDim.x;
    const size_t nq = (size_t)M_PAD * 512;
    const size_t nh = (size_t)2 * 3 * M_PAD * 256;
    const size_t nc = (size_t)3 * M_PAD * DIM;
    half z = __float2half_rn(0.0f);
    for (size_t i = gid; i < nq; i += stride) g_qstar[i] = z;
    for (size_t i = gid; i < nh; i += stride) g_hh[i] = z;
    for (size_t i = gid; i < nc; i += stride) g_c[i] = 0.0f;
    if (gid <= N_SEG) {
        int s = (int)gid;
        int lo = 0, hi = N_NODES;
        while (lo < hi) { int mid = (lo + hi) >> 1; if (seg[mid] < s) lo = mid + 1; else hi = mid; }
        g_start[s] = lo;
    }
}

// ---------------- pipeline constants --------------------------------------------
#define SM_BUF   16384
#define STAGE_SZ 32768
#define SMEM_GE  (3 * STAGE_SZ)

// ---------------- launch A: l0 full GEMM+LSTM  |  l1/l2 hh partials -------------
// grid (79, 8, 3). z=0: NC=12 full l0. z=1/2: NC=4 hh partial -> g_part.
__global__ __launch_bounds__(256, 2)
void gemmA(const half* __restrict__ qs, const half* __restrict__ wih0,
           const half* __restrict__ h0p, const half* __restrict__ whh0,
           const float* __restrict__ bias0, float* __restrict__ c0,
           half* __restrict__ h0out,
           const half* __restrict__ h1p, const half* __restrict__ whh1,
           const half* __restrict__ h2p, const half* __restrict__ whh2) {
    extern __shared__ __align__(128) char smem[];
    const uint32_t sbase = smem_u32(smem);
    const int tid = threadIdx.x;
    const int lane = tid & 31;
    const int wid = tid >> 5;
    const int bm = blockIdx.x * 128;
    const int bn = blockIdx.y * 128;
    const int z = blockIdx.z;

    const int r0 = tid >> 3;
    const int sg = tid & 7;
    const uint32_t so0 = (uint32_t)(r0 * 128 + ((sg * 16) ^ ((r0 & 7) << 4)));

    float4 acc[2][8];
#pragma unroll
    for (int i = 0; i < 2; i++)
#pragma unroll
        for (int j = 0; j < 8; j++) acc[i][j] = make_float4(0.f, 0.f, 0.f, 0.f);

    Frag frag = make_frag(sbase, wid, lane, SM_BUF);

    if (z == 0) {
        constexpr int C1 = 8, NC = 12;
        const half* a1p = qs + (size_t)(bm + r0) * 512 + sg * 8;
        const half* w1p = wih0 + (size_t)(bn + r0) * 512 + sg * 8;
        const half* a2p = h0p + (size_t)(bm + r0) * 256 + sg * 8;
        const half* w2p = whh0 + (size_t)(bn + r0) * 256 + sg * 8;

        auto load_chunk = [&](int g, int st) {
            const uint32_t sA = sbase + st * STAGE_SZ + so0;
            const uint32_t sB = sA + SM_BUF;
            if (g < C1) {
                const int off = g * 64;
#pragma unroll
                for (int q = 0; q < 4; q++) {
                    constexpr size_t ST = (size_t)32 * 512;
                    cp16(sA + q * 4096, a1p + q * ST + off);
                    cp16(sB + q * 4096, w1p + q * ST + off);
                }
            } else {
                const int off = (g - C1) * 64;
#pragma unroll
                for (int q = 0; q < 4; q++) {
                    constexpr size_t ST = (size_t)32 * 256;
                    cp16(sA + q * 4096, a2p + q * ST + off);
                    cp16(sB + q * 4096, w2p + q * ST + off);
                }
            }
            CP_COMMIT();
        };

        load_chunk(0, 0);
        load_chunk(1, 1);
        int st_cur = 0, st_nxt = 2;
#pragma unroll 1
        for (int g = 0; g < NC; g++) {
            if (g + 1 < NC) { CP_WAIT(1); } else { CP_WAIT(0); }
            __syncthreads();
            if (g + 2 < NC) load_chunk(g + 2, st_nxt);
            consume_chunk(frag, st_cur * STAGE_SZ, acc);
            st_cur = (st_cur == 2) ? 0 : st_cur + 1;
            st_nxt = (st_nxt == 2) ? 0 : st_nxt + 1;
        }
        lstm_epilogue(acc, lane, wid, bm, bn, bias0, c0, h0out, (float*)0, 0);
    } else {
        const half* A = (z == 1) ? h1p : h2p;
        const half* W = (z == 1) ? whh1 : whh2;
        const half* ap = A + (size_t)(bm + r0) * 256 + sg * 8;
        const half* wp = W + (size_t)(bn + r0) * 256 + sg * 8;

        auto load_chunk = [&](int g, int st) {
            const uint32_t sA = sbase + st * STAGE_SZ + so0;
            const uint32_t sB = sA + SM_BUF;
            const int off = g * 64;
#pragma unroll
            for (int q = 0; q < 4; q++) {
                constexpr size_t ST = (size_t)32 * 256;
                cp16(sA + q * 4096, ap + q * ST + off);
                cp16(sB + q * 4096, wp + q * ST + off);
            }
            CP_COMMIT();
        };

        load_chunk(0, 0);
        load_chunk(1, 1);
        int st_cur = 0, st_nxt = 2;
#pragma unroll 1
        for (int g = 0; g < 4; g++) {
            if (g + 1 < 4) { CP_WAIT(1); } else { CP_WAIT(0); }
            __syncthreads();
            if (g + 2 < 4) load_chunk(g + 2, st_nxt);
            consume_chunk(frag, st_cur * STAGE_SZ, acc);
            st_cur = (st_cur == 2) ? 0 : st_cur + 1;
            st_nxt = (st_nxt == 2) ? 0 : st_nxt + 1;
        }
        const size_t cta = (size_t)(z - 1) * NCTA + blockIdx.x * 8 + blockIdx.y;
        float4* pp = g_part + cta * (16 * 256) + tid;
#pragma unroll
        for (int i = 0; i < 2; i++)
#pragma unroll
            for (int j = 0; j < 8; j++) pp[(i * 8 + j) * 256] = acc[i][j];
    }
}

// ---------------- finish: ih GEMM (NC=4) + partial add + LSTM -------------------
__global__ __launch_bounds__(256, 2)
void gemmF(const half* __restrict__ A1, const half* __restrict__ W1,
           const float* __restrict__ bias, const float4* __restrict__ gpart,
           float* __restrict__ c, half* __restrict__ hout,
           float* __restrict__ hq, int write_q) {
    extern __shared__ __align__(128) char smem[];
    const uint32_t sbase = smem_u32(smem);
    const int tid = threadIdx.x;
    const int lane = tid & 31;
    const int wid = tid >> 5;
    const int bm = blockIdx.x * 128;
    const int bn = blockIdx.y * 128;

    const int r0 = tid >> 3;
    const int sg = tid & 7;
    const uint32_t so0 = (uint32_t)(r0 * 128 + ((sg * 16) ^ ((r0 & 7) << 4)));
    const half* ap = A1 + (size_t)(bm + r0) * 256 + sg * 8;
    const half* wp = W1 + (size_t)(bn + r0) * 256 + sg * 8;

    auto load_chunk = [&](int g, int st) {
        const uint32_t sA = sbase + st * STAGE_SZ + so0;
        const uint32_t sB = sA + SM_BUF;
        const int off = g * 64;
#pragma unroll
        for (int q = 0; q < 4; q++) {
            constexpr size_t ST = (size_t)32 * 256;
            cp16(sA + q * 4096, ap + q * ST + off);
            cp16(sB + q * 4096, wp + q * ST + off);
        }
        CP_COMMIT();
    };

    float4 acc[2][8];
#pragma unroll
    for (int i = 0; i < 2; i++)
#pragma unroll
        for (int j = 0; j < 8; j++) acc[i][j] = make_float4(0.f, 0.f, 0.f, 0.f);

    Frag frag = make_frag(sbase, wid, lane, SM_BUF);

    load_chunk(0, 0);
    load_chunk(1, 1);
    int st_cur = 0, st_nxt = 2;
#pragma unroll 1
    for (int g = 0; g < 4; g++) {
        if (g + 1 < 4) { CP_WAIT(1); } else { CP_WAIT(0); }
        __syncthreads();
        if (g + 2 < 4) load_chunk(g + 2, st_nxt);
        consume_chunk(frag, st_cur * STAGE_SZ, acc);
        st_cur = (st_cur == 2) ? 0 : st_cur + 1;
        st_nxt = (st_nxt == 2) ? 0 : st_nxt + 1;
    }

    const size_t cta = (size_t)blockIdx.x * 8 + blockIdx.y;
    const float4* pp = gpart + cta * (16 * 256) + tid;
#pragma unroll
    for (int i = 0; i < 2; i++)
#pragma unroll
        for (int j = 0; j < 8; j++) {
            float4 p = pp[(i * 8 + j) * 256];
            acc[i][j].x += p.x; acc[i][j].y += p.y;
            acc[i][j].z += p.z; acc[i][j].w += p.w;
        }

    lstm_epilogue(acc, lane, wid, bm, bn, bias, c, hout, hq, write_q);
}

// ---------------- fused attention (fp16 feats) -----------------------------------
__global__ void attn_kernel(const float* __restrict__ q, float* __restrict__ out) {
    const int s = blockIdx.x;
    const int lo = g_start[s], hi = g_start[s + 1];
    const int w = threadIdx.x >> 5;
    const int lane = threadIdx.x & 31;

    __shared__ float sm_m[8];
    __shared__ float sm_s[8];
    __shared__ float sm_r[8][256];

    float qf[8];
    *(float4*)&qf[0] = *(const float4*)(q + (size_t)s * DIM + lane * 8);
    *(float4*)&qf[4] = *(const float4*)(q + (size_t)s * DIM + lane * 8 + 4);

    float m = -INFINITY, ssum = 0.0f;
    float r[8];
#pragma unroll
    for (int j = 0; j < 8; j++) r[j] = 0.0f;

    for (int n = lo + w; n < hi; n += 8) {
        uint4 fv = *(const uint4*)(g_featsh + (size_t)n * DIM + lane * 8);
        float2 f0 = __half22float2(*(half2*)&fv.x);
        float2 f1 = __half22float2(*(half2*)&fv.y);
        float2 f2 = __half22float2(*(half2*)&fv.z);
        float2 f3 = __half22float2(*(half2*)&fv.w);
        float ff[8] = {f0.x, f0.y, f1.x, f1.y, f2.x, f2.y, f3.x, f3.y};
        float d = 0.0f;
#pragma unroll
        for (int j = 0; j < 8; j++) d = fmaf(ff[j], qf[j], d);
#pragma unroll
        for (int o = 16; o > 0; o >>= 1) d += __shfl_xor_sync(0xffffffffu, d, o);

        float mn = fmaxf(m, d);
        float sc = __expf(m - mn);
        float p  = __expf(d - mn);
        ssum = ssum * sc + p;
#pragma unroll
        for (int j = 0; j < 8; j++) r[j] = r[j] * sc + p * ff[j];
        m = mn;
    }

    if (lane == 0) { sm_m[w] = m; sm_s[w] = ssum; }
    *(float4*)&sm_r[w][lane * 8]     = *(float4*)&r[0];
    *(float4*)&sm_r[w][lane * 8 + 4] = *(float4*)&r[4];
    __syncthreads();

    const int t = threadIdx.x;
    float M = -INFINITY;
#pragma unroll
    for (int k = 0; k < 8; k++)
        if (sm_s[k] > 0.0f) M = fmaxf(M, sm_m[k]);
    float S = 0.0f, R = 0.0f;
#pragma unroll
    for (int k = 0; k < 8; k++) {
        if (sm_s[k] > 0.0f) {
            float sc = __expf(sm_m[k] - M);
            S += sm_s[k] * sc;
            R += sm_r[k][t] * sc;
        }
    }
    float rv = (S > 0.0f) ? R / S : 0.0f;
    float qv_ = q[(size_t)s * DIM + t];
    out[(size_t)s * QSTAR + t]       = qv_;
    out[(size_t)s * QSTAR + DIM + t] = rv;

    half* qs = g_qstar + (size_t)s * 512;
    qs[t]       = __float2half_rn(qv_);
    qs[256 + t] = __float2half_rn(rv);
}

// ---------------- host orchestration -------------------------------------------
extern "C" void kernel_launch(void* const* d_in, const int* in_sizes, int n_in,
                              void* d_out, int out_size) {
    const float* feats = (const float*)d_in[0];
    const int* seg = (const int*)d_in[1];
    float* out = (float*)d_out;

    PermArgs pa;
    for (int l = 0; l < 3; l++) {
        pa.w_ih[l] = (const float*)d_in[2 + 4 * l];
        pa.w_hh[l] = (const float*)d_in[3 + 4 * l];
        pa.b_ih[l] = (const float*)d_in[4 + 4 * l];
        pa.b_hh[l] = (const float*)d_in[5 + 4 * l];
        pa.K1[l] = (l == 0) ? QSTAR : DIM;
    }

    half *qs, *hh; float *c, *hq, *bp; half *wih[3], *whh[3]; float4* gpart;
    cudaGetSymbolAddress((void**)&qs, g_qstar);
    cudaGetSymbolAddress((void**)&hh, g_hh);
    cudaGetSymbolAddress((void**)&c, g_c);
    cudaGetSymbolAddress((void**)&hq, g_hq);
    cudaGetSymbolAddress((void**)&bp, g_bp);
    cudaGetSymbolAddress((void**)&gpart, g_part);
    {
        half* base_ih; half* base_hh;
        cudaGetSymbolAddress((void**)&base_ih, g_w_ih);
        cudaGetSymbolAddress((void**)&base_hh, g_w_hh);
        for (int l = 0; l < 3; l++) {
            wih[l] = base_ih + (size_t)l * NGATE * 512;
            whh[l] = base_hh + (size_t)l * NGATE * 256;
        }
    }

    cudaFuncSetAttribute(gemmA, cudaFuncAttributeMaxDynamicSharedMemorySize, SMEM_GE);
    cudaFuncSetAttribute(gemmF, cudaFuncAttributeMaxDynamicSharedMemorySize, SMEM_GE);

    dim3 pgrid(256, 3);
    prep_kernel<<<pgrid, 256>>>(pa);
    feats_conv_kernel<<<2048, 256>>>(feats);
    init_kernel<<<1184, 256>>>(seg);

    const size_t SDH = (size_t)M_PAD * 256;
    dim3 gA(M_PAD / 128, NGATE / 128, 3);
    dim3 gF(M_PAD / 128, NGATE / 128);

    for (int it = 0; it < NITER; it++) {
        half* hin  = hh + (size_t)(it & 1) * 3 * SDH;
        half* hout = hh + (size_t)((it + 1) & 1) * 3 * SDH;

        gemmA<<<gA, 256, SMEM_GE>>>(qs, wih[0], hin, whh[0], bp, c, hout,
                                    hin + 1 * SDH, whh[1],
                                    hin + 2 * SDH, whh[2]);
        gemmF<<<gF, 256, SMEM_GE>>>(hout, wih[1], bp + NGATE, gpart,
                                    c + 1 * (size_t)M_PAD * DIM, hout + 1 * SDH, hq, 0);
        gemmF<<<gF, 256, SMEM_GE>>>(hout + 1 * SDH, wih[2], bp + 2 * NGATE, gpart + PARTSZ,
                                    c + 2 * (size_t)M_PAD * DIM, hout + 2 * SDH, hq, 1);
        attn_kernel<<<N_SEG, 256>>>(hq, out);
    }
}

// round 16
// speedup vs baseline: 1.6432x; 1.0427x over previous
#include <cuda_runtime.h>
#include <cuda_fp16.h>
#include <math.h>
#include <stdint.h>

#define N_NODES 500000
#define N_SEG   10000
#define M_PAD   10112            // 79 * 128
#define DIM     256
#define NGATE   1024
#define QSTAR   512
#define NITER   6
#define NCTA    632              // 79 * 8 tiles per GEMM unit
#define PARTSZ  ((size_t)NCTA * 256 * 16)   // float4s per partial layer

// ---------------- scratch (device globals) -----------------------------------
__device__ half   g_featsh[(size_t)N_NODES * DIM];           // fp16 feats copy
__device__ half   g_qstar[(size_t)M_PAD * 512];              // fp16 [q|r]
__device__ half   g_hh[2 * 3 * (size_t)M_PAD * 256];          // fp16 h ping-pong x 3
__device__ float  g_c[3 * (size_t)M_PAD * DIM];
__device__ float  g_hq[(size_t)M_PAD * DIM];                  // fp32 q for attn
__device__ half   g_w_ih[3][(size_t)NGATE * 512];
__device__ half   g_w_hh[3][(size_t)NGATE * 256];
__device__ float  g_bp[3 * NGATE];
__device__ float4 g_part[2 * PARTSZ];                         // hh partial gates, 83 MB
__device__ int    g_start[N_SEG + 1];
// cross-CTA sync state (per iteration)
__device__ int    g_cnt_l0[NITER][79];                        // -> 8 when row-block done
__device__ int    g_cnt_l1[NITER][79];
__device__ int    g_hh_flag[NITER][2][NCTA];                  // per-tile hh partial ready

// ---------------- helpers ------------------------------------------------------
__device__ __forceinline__ uint32_t smem_u32(const void* p) {
    return (uint32_t)__cvta_generic_to_shared(p);
}
__device__ __forceinline__ void cp16(uint32_t dst, const void* src) {
    asm volatile("cp.async.cg.shared.global [%0], [%1], 16;" :: "r"(dst), "l"(src));
}
#define CP_COMMIT() asm volatile("cp.async.commit_group;" ::: "memory")
#define CP_WAIT(n)  asm volatile("cp.async.wait_group %0;" :: "n"(n) : "memory")

__device__ __forceinline__ void ldsm_x4(uint32_t& r0, uint32_t& r1, uint32_t& r2, uint32_t& r3,
                                        uint32_t addr) {
    asm volatile("ldmatrix.sync.aligned.m8n8.x4.shared.b16 {%0,%1,%2,%3}, [%4];"
        : "=r"(r0), "=r"(r1), "=r"(r2), "=r"(r3) : "r"(addr));
}
__device__ __forceinline__ void mma_f16(float4& d, const uint32_t* a, uint32_t b0, uint32_t b1) {
    asm volatile(
        "mma.sync.aligned.m16n8k16.row.col.f32.f16.f16.f32 "
        "{%0,%1,%2,%3}, {%4,%5,%6,%7}, {%8,%9}, {%0,%1,%2,%3};"
        : "+f"(d.x), "+f"(d.y), "+f"(d.z), "+f"(d.w)
        : "r"(a[0]), "r"(a[1]), "r"(a[2]), "r"(a[3]), "r"(b0), "r"(b1));
}

__device__ __forceinline__ float sigf(float x) { return 1.0f / (1.0f + __expf(-x)); }
__device__ __forceinline__ float tanhfast(float x) { return 2.0f / (1.0f + __expf(-2.0f * x)) - 1.0f; }

// fragment addressing (8 warps: 4 M x 2 N, warp tile 32x64)
struct Frag {
    uint32_t a_base[2], a_xc[2], b_base[4], b_xc[4];
};
__device__ __forceinline__ Frag make_frag(uint32_t sbase, int wid, int lane, uint32_t b_off) {
    Frag f;
    const int warp_m = wid & 3;
    const int warp_n = wid >> 2;
    const int koff = (lane >> 4) * 16;
#pragma unroll
    for (int tm = 0; tm < 2; tm++) {
        int row = warp_m * 32 + tm * 16 + (lane & 15);
        f.a_base[tm] = sbase + row * 128;
        f.a_xc[tm] = (uint32_t)(koff ^ ((row & 7) << 4));
    }
#pragma unroll
    for (int tn2 = 0; tn2 < 4; tn2++) {
        int row = warp_n * 64 + tn2 * 16 + (lane & 15);
        f.b_base[tn2] = sbase + b_off + row * 128;
        f.b_xc[tn2] = (uint32_t)(koff ^ ((row & 7) << 4));
    }
    return f;
}

__device__ __forceinline__ void consume_chunk(const Frag& f, uint32_t stoff, float4 (&acc)[2][8]) {
#pragma unroll
    for (int ks = 0; ks < 4; ks++) {
        uint32_t a[2][4];
#pragma unroll
        for (int tm = 0; tm < 2; tm++)
            ldsm_x4(a[tm][0], a[tm][1], a[tm][2], a[tm][3],
                    f.a_base[tm] + stoff + ((uint32_t)(ks * 32) ^ f.a_xc[tm]));
        uint32_t b[4][4];
#pragma unroll
        for (int tn2 = 0; tn2 < 4; tn2++)
            ldsm_x4(b[tn2][0], b[tn2][1], b[tn2][2], b[tn2][3],
                    f.b_base[tn2] + stoff + ((uint32_t)(ks * 32) ^ f.b_xc[tn2]));
#pragma unroll
        for (int tm = 0; tm < 2; tm++)
#pragma unroll
            for (int tn2 = 0; tn2 < 4; tn2++) {
                mma_f16(acc[tm][tn2 * 2 + 0], a[tm], b[tn2][0], b[tn2][2]);
                mma_f16(acc[tm][tn2 * 2 + 1], a[tm], b[tn2][1], b[tn2][3]);
            }
    }
}

__device__ __forceinline__ void lstm_epilogue(float4 (&acc)[2][8], int lane, int wid,
                                              int bm, int bn, const float* bias,
                                              float* c, half* hout, float* hq, int write_q) {
    const int warp_m = wid & 3;
    const int warp_n = wid >> 2;
    const bool even = !(lane & 1);
#pragma unroll
    for (int tm = 0; tm < 2; tm++) {
#pragma unroll
        for (int tn = 0; tn < 8; tn++) {
            float4 d = acc[tm][tn];
            float e0 = __shfl_xor_sync(0xffffffffu, d.x, 1);
            float e1 = __shfl_xor_sync(0xffffffffu, d.y, 1);
            float e2 = __shfl_xor_sync(0xffffffffu, d.z, 1);
            float e3 = __shfl_xor_sync(0xffffffffu, d.w, 1);
            if (even) {
                int col = bn + warp_n * 64 + tn * 8 + (lane & 3) * 2;
                int u = col >> 2;
                float4 bi = *(const float4*)&bias[col];
                int rA = bm + warp_m * 32 + tm * 16 + (lane >> 2);
#pragma unroll
                for (int rh = 0; rh < 2; rh++) {
                    int row = rA + rh * 8;
                    float gi = (rh ? d.z : d.x) + bi.x;
                    float gf = (rh ? d.w : d.y) + bi.y;
                    float gg = (rh ? e2 : e0) + bi.z;
                    float go = (rh ? e3 : e1) + bi.w;
                    size_t cidx = (size_t)row * DIM + u;
                    float cn = sigf(gf) * c[cidx] + sigf(gi) * tanhfast(gg);
                    c[cidx] = cn;
                    float hn = sigf(go) * tanhfast(cn);
                    hout[(size_t)row * 256 + u] = __float2half_rn(hn);
                    if (write_q) hq[(size_t)row * DIM + u] = hn;
                }
            }
        }
    }
}

// ---------------- prep / conv / init ----------------------------------------------
struct PermArgs {
    const float* w_ih[3]; const float* w_hh[3];
    const float* b_ih[3]; const float* b_hh[3];
    int K1[3];
};
__global__ void prep_kernel(PermArgs pa) {
    int l = blockIdx.y;
    int K1 = pa.K1[l];
    half* wih = g_w_ih[l];
    half* whh = g_w_hh[l];
    int n_ih = NGATE * K1, n_hh = NGATE * DIM;
    int total = n_ih + n_hh + NGATE;
    for (int i = blockIdx.x * blockDim.x + threadIdx.x; i < total; i += gridDim.x * blockDim.x) {
        if (i < n_ih) {
            int r = i / K1, k = i - r * K1;
            int u = r >> 2, g = r & 3;
            wih[i] = __float2half_rn(pa.w_ih[l][(size_t)(g * 256 + u) * K1 + k]);
        } else if (i < n_ih + n_hh) {
            int j = i - n_ih;
            int r = j / DIM, k = j - r * DIM;
            int u = r >> 2, g = r & 3;
            whh[j] = __float2half_rn(pa.w_hh[l][(size_t)(g * 256 + u) * DIM + k]);
        } else {
            int r = i - n_ih - n_hh;
            int u = r >> 2, g = r & 3;
            g_bp[l * NGATE + r] = pa.b_ih[l][g * 256 + u] + pa.b_hh[l][g * 256 + u];
        }
    }
}

__global__ void feats_conv_kernel(const float* __restrict__ feats) {
    size_t i = ((size_t)blockIdx.x * blockDim.x + threadIdx.x) * 4;
    size_t stride = (size_t)gridDim.x * blockDim.x * 4;
    const size_t n = (size_t)N_NODES * DIM;
    for (; i < n; i += stride) {
        float4 v = *(const float4*)(feats + i);
        half2 h0 = __floats2half2_rn(v.x, v.y);
        half2 h1 = __floats2half2_rn(v.z, v.w);
        *(uint2*)(g_featsh + i) = make_uint2(*(uint32_t*)&h0, *(uint32_t*)&h1);
    }
}

__global__ void init_kernel(const int* __restrict__ seg) {
    size_t gid = (size_t)blockIdx.x * blockDim.x + threadIdx.x;
    size_t stride = (size_t)gridDim.x * blockDim.x;
    const size_t nq = (size_t)M_PAD * 512;
    const size_t nh = (size_t)2 * 3 * M_PAD * 256;
    const size_t nc = (size_t)3 * M_PAD * DIM;
    half z = __float2half_rn(0.0f);
    for (size_t i = gid; i < nq; i += stride) g_qstar[i] = z;
    for (size_t i = gid; i < nh; i += stride) g_hh[i] = z;
    for (size_t i = gid; i < nc; i += stride) g_c[i] = 0.0f;
    // reset sync state
    if (gid < NITER * 79) {
        ((int*)g_cnt_l0)[gid] = 0;
        ((int*)g_cnt_l1)[gid] = 0;
    }
    if (gid < (size_t)NITER * 2 * NCTA) ((int*)g_hh_flag)[gid] = 0;
    if (gid <= N_SEG) {
        int s = (int)gid;
        int lo = 0, hi = N_NODES;
        while (lo < hi) { int mid = (lo + hi) >> 1; if (seg[mid] < s) lo = mid + 1; else hi = mid; }
        g_start[s] = lo;
    }
}

// ---------------- pipeline constants --------------------------------------------
#define SM_BUF   16384
#define STAGE_SZ 32768
#define SMEM_GE  (3 * STAGE_SZ)

// ---------------- merged per-iteration GEMM kernel -------------------------------
// blockIdx.x (1D, 3160 CTAs):
//   [0, 632)      l0 full GEMM + LSTM           (producer: cnt_l0[bm])
//   [632, 1264)   l1 hh partial -> g_part       (producer: hh_flag[0][tile])
//   [1264, 1896)  l2 hh partial -> g_part       (producer: hh_flag[1][tile])
//   [1896, 2528)  l1 finish (waits cnt_l0[bm]==8 & hh_flag[0]) (producer: cnt_l1[bm])
//   [2528, 3160)  l2 finish (waits cnt_l1[bm]==8 & hh_flag[1]) -> writes hq
__global__ __launch_bounds__(256, 2)
void gemm_all(const half* __restrict__ qs,
              const half* __restrict__ h0p,   // prev-iter h (all 3 layers, stride SDH)
              half* __restrict__ hnew,        // this-iter h base (3 layers)
              float* __restrict__ c,
              float* __restrict__ hq, int it) {
    extern __shared__ __align__(128) char smem[];
    const uint32_t sbase = smem_u32(smem);
    const int tid = threadIdx.x;
    const int lane = tid & 31;
    const int wid = tid >> 5;
    const size_t SDH = (size_t)M_PAD * 256;

    const int cid = blockIdx.x;
    int phase, t632;
    if (cid < 632)       { phase = 0; t632 = cid; }
    else if (cid < 1264) { phase = 1; t632 = cid - 632; }
    else if (cid < 1896) { phase = 2; t632 = cid - 1264; }
    else if (cid < 2528) { phase = 3; t632 = cid - 1896; }
    else                 { phase = 4; t632 = cid - 2528; }
    const int bx = t632 >> 3;          // 0..78
    const int by = t632 & 7;
    const int bm = bx * 128;
    const int bn = by * 128;

    const int r0 = tid >> 3;
    const int sg = tid & 7;
    const uint32_t so0 = (uint32_t)(r0 * 128 + ((sg * 16) ^ ((r0 & 7) << 4)));

    float4 acc[2][8];
#pragma unroll
    for (int i = 0; i < 2; i++)
#pragma unroll
        for (int j = 0; j < 8; j++) acc[i][j] = make_float4(0.f, 0.f, 0.f, 0.f);

    Frag frag = make_frag(sbase, wid, lane, SM_BUF);

    if (phase == 0) {
        // ---- l0 full: qs(K=512)@wih0 + h0(K=256)@whh0 ----
        constexpr int C1 = 8, NC = 12;
        const half* a1p = qs + (size_t)(bm + r0) * 512 + sg * 8;
        const half* w1p = g_w_ih[0] + (size_t)(bn + r0) * 512 + sg * 8;
        const half* a2p = h0p + (size_t)(bm + r0) * 256 + sg * 8;
        const half* w2p = g_w_hh[0] + (size_t)(bn + r0) * 256 + sg * 8;

        auto load_chunk = [&](int g, int st) {
            const uint32_t sA = sbase + st * STAGE_SZ + so0;
            const uint32_t sB = sA + SM_BUF;
            if (g < C1) {
                const int off = g * 64;
#pragma unroll
                for (int q = 0; q < 4; q++) {
                    constexpr size_t ST = (size_t)32 * 512;
                    cp16(sA + q * 4096, a1p + q * ST + off);
                    cp16(sB + q * 4096, w1p + q * ST + off);
                }
            } else {
                const int off = (g - C1) * 64;
#pragma unroll
                for (int q = 0; q < 4; q++) {
                    constexpr size_t ST = (size_t)32 * 256;
                    cp16(sA + q * 4096, a2p + q * ST + off);
                    cp16(sB + q * 4096, w2p + q * ST + off);
                }
            }
            CP_COMMIT();
        };

        load_chunk(0, 0);
        load_chunk(1, 1);
        int st_cur = 0, st_nxt = 2;
#pragma unroll 1
        for (int g = 0; g < NC; g++) {
            if (g + 1 < NC) { CP_WAIT(1); } else { CP_WAIT(0); }
            __syncthreads();
            if (g + 2 < NC) load_chunk(g + 2, st_nxt);
            consume_chunk(frag, st_cur * STAGE_SZ, acc);
            st_cur = (st_cur == 2) ? 0 : st_cur + 1;
            st_nxt = (st_nxt == 2) ? 0 : st_nxt + 1;
        }
        lstm_epilogue(acc, lane, wid, bm, bn, g_bp, c, hnew, (float*)0, 0);
        __threadfence();
        __syncthreads();
        if (tid == 0) atomicAdd(&g_cnt_l0[it][bx], 1);

    } else if (phase <= 2) {
        // ---- hh partial: h_prev[layer] @ whh[layer] ----
        const int lay = phase;                       // 1 or 2
        const half* ap = h0p + (size_t)lay * SDH + (size_t)(bm + r0) * 256 + sg * 8;
        const half* wp = g_w_hh[lay] + (size_t)(bn + r0) * 256 + sg * 8;

        auto load_chunk = [&](int g, int st) {
            const uint32_t sA = sbase + st * STAGE_SZ + so0;
            const uint32_t sB = sA + SM_BUF;
            const int off = g * 64;
#pragma unroll
            for (int q = 0; q < 4; q++) {
                constexpr size_t ST = (size_t)32 * 256;
                cp16(sA + q * 4096, ap + q * ST + off);
                cp16(sB + q * 4096, wp + q * ST + off);
            }
            CP_COMMIT();
        };

        load_chunk(0, 0);
        load_chunk(1, 1);
        int st_cur = 0, st_nxt = 2;
#pragma unroll 1
        for (int g = 0; g < 4; g++) {
            if (g + 1 < 4) { CP_WAIT(1); } else { CP_WAIT(0); }
            __syncthreads();
            if (g + 2 < 4) load_chunk(g + 2, st_nxt);
            consume_chunk(frag, st_cur * STAGE_SZ, acc);
            st_cur = (st_cur == 2) ? 0 : st_cur + 1;
            st_nxt = (st_nxt == 2) ? 0 : st_nxt + 1;
        }
        float4* pp = g_part + (size_t)(lay - 1) * PARTSZ + (size_t)t632 * (16 * 256) + tid;
#pragma unroll
        for (int i = 0; i < 2; i++)
#pragma unroll
            for (int j = 0; j < 8; j++) pp[(i * 8 + j) * 256] = acc[i][j];
        __threadfence();
        __syncthreads();
        if (tid == 0) atomicExch(&g_hh_flag[it][lay - 1][t632], 1);

    } else {
        // ---- finish: ih GEMM on fresh h + partial add + LSTM ----
        const int lay = phase - 2;                   // 1 or 2
        // wait for producers
        if (tid == 0) {
            volatile int* cnt = (lay == 1) ? &g_cnt_l0[it][bx] : &g_cnt_l1[it][bx];
            while (*cnt < 8) { }
            volatile int* hf = &g_hh_flag[it][lay - 1][t632];
            while (*hf == 0) { }
            __threadfence();
        }
        __syncthreads();

        const half* A1 = hnew + (size_t)(lay - 1) * SDH;
        const half* ap = A1 + (size_t)(bm + r0) * 256 + sg * 8;
        const half* wp = g_w_ih[lay] + (size_t)(bn + r0) * 256 + sg * 8;

        auto load_chunk = [&](int g, int st) {
            const uint32_t sA = sbase + st * STAGE_SZ + so0;
            const uint32_t sB = sA + SM_BUF;
            const int off = g * 64;
#pragma unroll
            for (int q = 0; q < 4; q++) {
                constexpr size_t ST = (size_t)32 * 256;
                cp16(sA + q * 4096, ap + q * ST + off);
                cp16(sB + q * 4096, wp + q * ST + off);
            }
            CP_COMMIT();
        };

        load_chunk(0, 0);
        load_chunk(1, 1);
        int st_cur = 0, st_nxt = 2;
#pragma unroll 1
        for (int g = 0; g < 4; g++) {
            if (g + 1 < 4) { CP_WAIT(1); } else { CP_WAIT(0); }
            __syncthreads();
            if (g + 2 < 4) load_chunk(g + 2, st_nxt);
            consume_chunk(frag, st_cur * STAGE_SZ, acc);
            st_cur = (st_cur == 2) ? 0 : st_cur + 1;
            st_nxt = (st_nxt == 2) ? 0 : st_nxt + 1;
        }

        const float4* pp = g_part + (size_t)(lay - 1) * PARTSZ + (size_t)t632 * (16 * 256) + tid;
#pragma unroll
        for (int i = 0; i < 2; i++)
#pragma unroll
            for (int j = 0; j < 8; j++) {
                float4 p = pp[(i * 8 + j) * 256];
                acc[i][j].x += p.x; acc[i][j].y += p.y;
                acc[i][j].z += p.z; acc[i][j].w += p.w;
            }

        lstm_epilogue(acc, lane, wid, bm, bn, g_bp + lay * NGATE,
                      c + (size_t)lay * M_PAD * DIM,
                      hnew + (size_t)lay * SDH, hq, (lay == 2) ? 1 : 0);
        if (lay == 1) {
            __threadfence();
            __syncthreads();
            if (tid == 0) atomicAdd(&g_cnt_l1[it][bx], 1);
        }
    }
}

// ---------------- fused attention (fp16 feats) -----------------------------------
__global__ void attn_kernel(const float* __restrict__ q, float* __restrict__ out) {
    const int s = blockIdx.x;
    const int lo = g_start[s], hi = g_start[s + 1];
    const int w = threadIdx.x >> 5;
    const int lane = threadIdx.x & 31;

    __shared__ float sm_m[8];
    __shared__ float sm_s[8];
    __shared__ float sm_r[8][256];

    float qf[8];
    *(float4*)&qf[0] = *(const float4*)(q + (size_t)s * DIM + lane * 8);
    *(float4*)&qf[4] = *(const float4*)(q + (size_t)s * DIM + lane * 8 + 4);

    float m = -INFINITY, ssum = 0.0f;
    float r[8];
#pragma unroll
    for (int j = 0; j < 8; j++) r[j] = 0.0f;

    for (int n = lo + w; n < hi; n += 8) {
        uint4 fv = *(const uint4*)(g_featsh + (size_t)n * DIM + lane * 8);
        float2 f0 = __half22float2(*(half2*)&fv.x);
        float2 f1 = __half22float2(*(half2*)&fv.y);
        float2 f2 = __half22float2(*(half2*)&fv.z);
        float2 f3 = __half22float2(*(half2*)&fv.w);
        float ff[8] = {f0.x, f0.y, f1.x, f1.y, f2.x, f2.y, f3.x, f3.y};
        float d = 0.0f;
#pragma unroll
        for (int j = 0; j < 8; j++) d = fmaf(ff[j], qf[j], d);
#pragma unroll
        for (int o = 16; o > 0; o >>= 1) d += __shfl_xor_sync(0xffffffffu, d, o);

        float mn = fmaxf(m, d);
        float sc = __expf(m - mn);
        float p  = __expf(d - mn);
        ssum = ssum * sc + p;
#pragma unroll
        for (int j = 0; j < 8; j++) r[j] = r[j] * sc + p * ff[j];
        m = mn;
    }

    if (lane == 0) { sm_m[w] = m; sm_s[w] = ssum; }
    *(float4*)&sm_r[w][lane * 8]     = *(float4*)&r[0];
    *(float4*)&sm_r[w][lane * 8 + 4] = *(float4*)&r[4];
    __syncthreads();

    const int t = threadIdx.x;
    float M = -INFINITY;
#pragma unroll
    for (int k = 0; k < 8; k++)
        if (sm_s[k] > 0.0f) M = fmaxf(M, sm_m[k]);
    float S = 0.0f, R = 0.0f;
#pragma unroll
    for (int k = 0; k < 8; k++) {
        if (sm_s[k] > 0.0f) {
            float sc = __expf(sm_m[k] - M);
            S += sm_s[k] * sc;
            R += sm_r[k][t] * sc;
        }
    }
    float rv = (S > 0.0f) ? R / S : 0.0f;
    float qv_ = q[(size_t)s * DIM + t];
    out[(size_t)s * QSTAR + t]       = qv_;
    out[(size_t)s * QSTAR + DIM + t] = rv;

    half* qs = g_qstar + (size_t)s * 512;
    qs[t]       = __float2half_rn(qv_);
    qs[256 + t] = __float2half_rn(rv);
}

// ---------------- host orchestration -------------------------------------------
extern "C" void kernel_launch(void* const* d_in, const int* in_sizes, int n_in,
                              void* d_out, int out_size) {
    const float* feats = (const float*)d_in[0];
    const int* seg = (const int*)d_in[1];
    float* out = (float*)d_out;

    PermArgs pa;
    for (int l = 0; l < 3; l++) {
        pa.w_ih[l] = (const float*)d_in[2 + 4 * l];
        pa.w_hh[l] = (const float*)d_in[3 + 4 * l];
        pa.b_ih[l] = (const float*)d_in[4 + 4 * l];
        pa.b_hh[l] = (const float*)d_in[5 + 4 * l];
        pa.K1[l] = (l == 0) ? QSTAR : DIM;
    }

    half *qs, *hh; float *c, *hq;
    cudaGetSymbolAddress((void**)&qs, g_qstar);
    cudaGetSymbolAddress((void**)&hh, g_hh);
    cudaGetSymbolAddress((void**)&c, g_c);
    cudaGetSymbolAddress((void**)&hq, g_hq);

    cudaFuncSetAttribute(gemm_all, cudaFuncAttributeMaxDynamicSharedMemorySize, SMEM_GE);

    dim3 pgrid(256, 3);
    prep_kernel<<<pgrid, 256>>>(pa);
    feats_conv_kernel<<<2048, 256>>>(feats);
    init_kernel<<<1184, 256>>>(seg);

    const size_t SDH = (size_t)M_PAD * 256;

    for (int it = 0; it < NITER; it++) {
        half* hin  = hh + (size_t)(it & 1) * 3 * SDH;
        half* hout = hh + (size_t)((it + 1) & 1) * 3 * SDH;
        gemm_all<<<3160, 256, SMEM_GE>>>(qs, hin, hout, c, hq, it);
        attn_kernel<<<N_SEG, 256>>>(hq, out);
    }
}

// round 17
// speedup vs baseline: 1.7817x; 1.0842x over previous
#include <cuda_runtime.h>
#include <cuda_fp16.h>
#include <math.h>
#include <stdint.h>

#define N_NODES 500000
#define N_SEG   10000
#define M_PAD   10112            // 79 * 128
#define DIM     256
#define NGATE   1024
#define QSTAR   512
#define NITER   6

// ---------------- scratch (device globals) -----------------------------------
__device__ half   g_featsh[(size_t)N_NODES * DIM];           // fp16 feats copy
__device__ half   g_qstar[(size_t)M_PAD * 512];              // fp16 [q|r]
__device__ half   g_hh[2 * 3 * (size_t)M_PAD * 256];          // fp16 h ping-pong x 3
__device__ float  g_c[3 * (size_t)M_PAD * DIM];
__device__ float  g_hq[(size_t)M_PAD * DIM];                  // fp32 q for attn
__device__ half   g_w_ih[3][(size_t)NGATE * 512];
__device__ half   g_w_hh[3][(size_t)NGATE * 256];
__device__ float  g_bp[3 * NGATE];
__device__ int    g_start[N_SEG + 1];
// cross-CTA sync state (per iteration)
__device__ int    g_cnt_l0[NITER][79];                        // -> 8 when row-block done
__device__ int    g_cnt_l1[NITER][79];

// ---------------- helpers ------------------------------------------------------
__device__ __forceinline__ uint32_t smem_u32(const void* p) {
    return (uint32_t)__cvta_generic_to_shared(p);
}
__device__ __forceinline__ void cp16(uint32_t dst, const void* src) {
    asm volatile("cp.async.cg.shared.global [%0], [%1], 16;" :: "r"(dst), "l"(src));
}
#define CP_COMMIT() asm volatile("cp.async.commit_group;" ::: "memory")
#define CP_WAIT(n)  asm volatile("cp.async.wait_group %0;" :: "n"(n) : "memory")

__device__ __forceinline__ void ldsm_x4(uint32_t& r0, uint32_t& r1, uint32_t& r2, uint32_t& r3,
                                        uint32_t addr) {
    asm volatile("ldmatrix.sync.aligned.m8n8.x4.shared.b16 {%0,%1,%2,%3}, [%4];"
        : "=r"(r0), "=r"(r1), "=r"(r2), "=r"(r3) : "r"(addr));
}
__device__ __forceinline__ void mma_f16(float4& d, const uint32_t* a, uint32_t b0, uint32_t b1) {
    asm volatile(
        "mma.sync.aligned.m16n8k16.row.col.f32.f16.f16.f32 "
        "{%0,%1,%2,%3}, {%4,%5,%6,%7}, {%8,%9}, {%0,%1,%2,%3};"
        : "+f"(d.x), "+f"(d.y), "+f"(d.z), "+f"(d.w)
        : "r"(a[0]), "r"(a[1]), "r"(a[2]), "r"(a[3]), "r"(b0), "r"(b1));
}

__device__ __forceinline__ float sigf(float x) { return 1.0f / (1.0f + __expf(-x)); }
__device__ __forceinline__ float tanhfast(float x) { return 2.0f / (1.0f + __expf(-2.0f * x)) - 1.0f; }

// fragment addressing (8 warps: 4 M x 2 N, warp tile 32x64)
struct Frag {
    uint32_t a_base[2], a_xc[2], b_base[4], b_xc[4];
};
__device__ __forceinline__ Frag make_frag(uint32_t sbase, int wid, int lane, uint32_t b_off) {
    Frag f;
    const int warp_m = wid & 3;
    const int warp_n = wid >> 2;
    const int koff = (lane >> 4) * 16;
#pragma unroll
    for (int tm = 0; tm < 2; tm++) {
        int row = warp_m * 32 + tm * 16 + (lane & 15);
        f.a_base[tm] = sbase + row * 128;
        f.a_xc[tm] = (uint32_t)(koff ^ ((row & 7) << 4));
    }
#pragma unroll
    for (int tn2 = 0; tn2 < 4; tn2++) {
        int row = warp_n * 64 + tn2 * 16 + (lane & 15);
        f.b_base[tn2] = sbase + b_off + row * 128;
        f.b_xc[tn2] = (uint32_t)(koff ^ ((row & 7) << 4));
    }
    return f;
}

__device__ __forceinline__ void consume_chunk(const Frag& f, uint32_t stoff, float4 (&acc)[2][8]) {
#pragma unroll
    for (int ks = 0; ks < 4; ks++) {
        uint32_t a[2][4];
#pragma unroll
        for (int tm = 0; tm < 2; tm++)
            ldsm_x4(a[tm][0], a[tm][1], a[tm][2], a[tm][3],
                    f.a_base[tm] + stoff + ((uint32_t)(ks * 32) ^ f.a_xc[tm]));
        uint32_t b[4][4];
#pragma unroll
        for (int tn2 = 0; tn2 < 4; tn2++)
            ldsm_x4(b[tn2][0], b[tn2][1], b[tn2][2], b[tn2][3],
                    f.b_base[tn2] + stoff + ((uint32_t)(ks * 32) ^ f.b_xc[tn2]));
#pragma unroll
        for (int tm = 0; tm < 2; tm++)
#pragma unroll
            for (int tn2 = 0; tn2 < 4; tn2++) {
                mma_f16(acc[tm][tn2 * 2 + 0], a[tm], b[tn2][0], b[tn2][2]);
                mma_f16(acc[tm][tn2 * 2 + 1], a[tm], b[tn2][1], b[tn2][3]);
            }
    }
}

// 4-chunk pipelined GEMM over K=256 source (row stride 256 halves)
__device__ __forceinline__ void gemm256(const half* ap, const half* wp,
                                        uint32_t sbase, uint32_t so0,
                                        const Frag& frag, float4 (&acc)[2][8]) {
    auto load_chunk = [&](int g, int st) {
        const uint32_t sA = sbase + st * 32768u + so0;
        const uint32_t sB = sA + 16384u;
        const int off = g * 64;
#pragma unroll
        for (int q = 0; q < 4; q++) {
            constexpr size_t ST = (size_t)32 * 256;
            cp16(sA + q * 4096, ap + q * ST + off);
            cp16(sB + q * 4096, wp + q * ST + off);
        }
        CP_COMMIT();
    };
    load_chunk(0, 0);
    load_chunk(1, 1);
    int st_cur = 0, st_nxt = 2;
#pragma unroll 1
    for (int g = 0; g < 4; g++) {
        if (g + 1 < 4) { CP_WAIT(1); } else { CP_WAIT(0); }
        __syncthreads();
        if (g + 2 < 4) load_chunk(g + 2, st_nxt);
        consume_chunk(frag, st_cur * 32768u, acc);
        st_cur = (st_cur == 2) ? 0 : st_cur + 1;
        st_nxt = (st_nxt == 2) ? 0 : st_nxt + 1;
    }
}

__device__ __forceinline__ void lstm_epilogue(float4 (&acc)[2][8], int lane, int wid,
                                              int bm, int bn, const float* bias,
                                              float* c, half* hout, float* hq, int write_q) {
    const int warp_m = wid & 3;
    const int warp_n = wid >> 2;
    const bool even = !(lane & 1);
#pragma unroll
    for (int tm = 0; tm < 2; tm++) {
#pragma unroll
        for (int tn = 0; tn < 8; tn++) {
            float4 d = acc[tm][tn];
            float e0 = __shfl_xor_sync(0xffffffffu, d.x, 1);
            float e1 = __shfl_xor_sync(0xffffffffu, d.y, 1);
            float e2 = __shfl_xor_sync(0xffffffffu, d.z, 1);
            float e3 = __shfl_xor_sync(0xffffffffu, d.w, 1);
            if (even) {
                int col = bn + warp_n * 64 + tn * 8 + (lane & 3) * 2;
                int u = col >> 2;
                float4 bi = *(const float4*)&bias[col];
                int rA = bm + warp_m * 32 + tm * 16 + (lane >> 2);
#pragma unroll
                for (int rh = 0; rh < 2; rh++) {
                    int row = rA + rh * 8;
                    float gi = (rh ? d.z : d.x) + bi.x;
                    float gf = (rh ? d.w : d.y) + bi.y;
                    float gg = (rh ? e2 : e0) + bi.z;
                    float go = (rh ? e3 : e1) + bi.w;
                    size_t cidx = (size_t)row * DIM + u;
                    float cn = sigf(gf) * c[cidx] + sigf(gi) * tanhfast(gg);
                    c[cidx] = cn;
                    float hn = sigf(go) * tanhfast(cn);
                    hout[(size_t)row * 256 + u] = __float2half_rn(hn);
                    if (write_q) hq[(size_t)row * DIM + u] = hn;
                }
            }
        }
    }
}

// ---------------- prep / conv / init ----------------------------------------------
struct PermArgs {
    const float* w_ih[3]; const float* w_hh[3];
    const float* b_ih[3]; const float* b_hh[3];
    int K1[3];
};
__global__ void prep_kernel(PermArgs pa) {
    int l = blockIdx.y;
    int K1 = pa.K1[l];
    half* wih = g_w_ih[l];
    half* whh = g_w_hh[l];
    int n_ih = NGATE * K1, n_hh = NGATE * DIM;
    int total = n_ih + n_hh + NGATE;
    for (int i = blockIdx.x * blockDim.x + threadIdx.x; i < total; i += gridDim.x * blockDim.x) {
        if (i < n_ih) {
            int r = i / K1, k = i - r * K1;
            int u = r >> 2, g = r & 3;
            wih[i] = __float2half_rn(pa.w_ih[l][(size_t)(g * 256 + u) * K1 + k]);
        } else if (i < n_ih + n_hh) {
            int j = i - n_ih;
            int r = j / DIM, k = j - r * DIM;
            int u = r >> 2, g = r & 3;
            whh[j] = __float2half_rn(pa.w_hh[l][(size_t)(g * 256 + u) * DIM + k]);
        } else {
            int r = i - n_ih - n_hh;
            int u = r >> 2, g = r & 3;
            g_bp[l * NGATE + r] = pa.b_ih[l][g * 256 + u] + pa.b_hh[l][g * 256 + u];
        }
    }
}

__global__ void feats_conv_kernel(const float* __restrict__ feats) {
    size_t i = ((size_t)blockIdx.x * blockDim.x + threadIdx.x) * 4;
    size_t stride = (size_t)gridDim.x * blockDim.x * 4;
    const size_t n = (size_t)N_NODES * DIM;
    for (; i < n; i += stride) {
        float4 v = *(const float4*)(feats + i);
        half2 h0 = __floats2half2_rn(v.x, v.y);
        half2 h1 = __floats2half2_rn(v.z, v.w);
        *(uint2*)(g_featsh + i) = make_uint2(*(uint32_t*)&h0, *(uint32_t*)&h1);
    }
}

__global__ void init_kernel(const int* __restrict__ seg) {
    size_t gid = (size_t)blockIdx.x * blockDim.x + threadIdx.x;
    size_t stride = (size_t)gridDim.x * blockDim.x;
    const size_t nq = (size_t)M_PAD * 512;
    const size_t nh = (size_t)2 * 3 * M_PAD * 256;
    const size_t nc = (size_t)3 * M_PAD * DIM;
    half z = __float2half_rn(0.0f);
    for (size_t i = gid; i < nq; i += stride) g_qstar[i] = z;
    for (size_t i = gid; i < nh; i += stride) g_hh[i] = z;
    for (size_t i = gid; i < nc; i += stride) g_c[i] = 0.0f;
    if (gid < NITER * 79) {
        ((int*)g_cnt_l0)[gid] = 0;
        ((int*)g_cnt_l1)[gid] = 0;
    }
    if (gid <= N_SEG) {
        int s = (int)gid;
        int lo = 0, hi = N_NODES;
        while (lo < hi) { int mid = (lo + hi) >> 1; if (seg[mid] < s) lo = mid + 1; else hi = mid; }
        g_start[s] = lo;
    }
}

// ---------------- pipeline constants --------------------------------------------
#define SM_BUF   16384
#define STAGE_SZ 32768
#define SMEM_GE  (3 * STAGE_SZ)

// ---------------- merged per-iteration GEMM kernel -------------------------------
// grid 1896 (1D):
//   [0, 632)      l0 full (NC=12) + LSTM          -> cnt_l0[bx]
//   [632, 1264)   l1: hh GEMM, wait cnt_l0==8, ih GEMM, LSTM -> cnt_l1[bx]
//   [1264, 1896)  l2: hh GEMM, wait cnt_l1==8, ih GEMM, LSTM -> hq
__global__ __launch_bounds__(256, 2)
void gemm_all(const half* __restrict__ qs,
              const half* __restrict__ h0p,   // prev-iter h (3 layers, stride SDH)
              half* __restrict__ hnew,        // this-iter h base (3 layers)
              float* __restrict__ c,
              float* __restrict__ hq, int it) {
    extern __shared__ __align__(128) char smem[];
    const uint32_t sbase = smem_u32(smem);
    const int tid = threadIdx.x;
    const int lane = tid & 31;
    const int wid = tid >> 5;
    const size_t SDH = (size_t)M_PAD * 256;

    const int cid = blockIdx.x;
    int phase, t632;
    if (cid < 632)       { phase = 0; t632 = cid; }
    else if (cid < 1264) { phase = 1; t632 = cid - 632; }
    else                 { phase = 2; t632 = cid - 1264; }
    const int bx = t632 >> 3;
    const int by = t632 & 7;
    const int bm = bx * 128;
    const int bn = by * 128;

    const int r0 = tid >> 3;
    const int sg = tid & 7;
    const uint32_t so0 = (uint32_t)(r0 * 128 + ((sg * 16) ^ ((r0 & 7) << 4)));

    float4 acc[2][8];
#pragma unroll
    for (int i = 0; i < 2; i++)
#pragma unroll
        for (int j = 0; j < 8; j++) acc[i][j] = make_float4(0.f, 0.f, 0.f, 0.f);

    Frag frag = make_frag(sbase, wid, lane, SM_BUF);

    if (phase == 0) {
        // ---- l0 full: qs(K=512)@wih0 + h0(K=256)@whh0, NC=12 ----
        constexpr int C1 = 8, NC = 12;
        const half* a1p = qs + (size_t)(bm + r0) * 512 + sg * 8;
        const half* w1p = g_w_ih[0] + (size_t)(bn + r0) * 512 + sg * 8;
        const half* a2p = h0p + (size_t)(bm + r0) * 256 + sg * 8;
        const half* w2p = g_w_hh[0] + (size_t)(bn + r0) * 256 + sg * 8;

        auto load_chunk = [&](int g, int st) {
            const uint32_t sA = sbase + st * STAGE_SZ + so0;
            const uint32_t sB = sA + SM_BUF;
            if (g < C1) {
                const int off = g * 64;
#pragma unroll
                for (int q = 0; q < 4; q++) {
                    constexpr size_t ST = (size_t)32 * 512;
                    cp16(sA + q * 4096, a1p + q * ST + off);
                    cp16(sB + q * 4096, w1p + q * ST + off);
                }
            } else {
                const int off = (g - C1) * 64;
#pragma unroll
                for (int q = 0; q < 4; q++) {
                    constexpr size_t ST = (size_t)32 * 256;
                    cp16(sA + q * 4096, a2p + q * ST + off);
                    cp16(sB + q * 4096, w2p + q * ST + off);
                }
            }
            CP_COMMIT();
        };

        load_chunk(0, 0);
        load_chunk(1, 1);
        int st_cur = 0, st_nxt = 2;
#pragma unroll 1
        for (int g = 0; g < NC; g++) {
            if (g + 1 < NC) { CP_WAIT(1); } else { CP_WAIT(0); }
            __syncthreads();
            if (g + 2 < NC) load_chunk(g + 2, st_nxt);
            consume_chunk(frag, st_cur * STAGE_SZ, acc);
            st_cur = (st_cur == 2) ? 0 : st_cur + 1;
            st_nxt = (st_nxt == 2) ? 0 : st_nxt + 1;
        }
        lstm_epilogue(acc, lane, wid, bm, bn, g_bp, c, hnew, (float*)0, 0);
        __threadfence();
        __syncthreads();
        if (tid == 0) atomicAdd(&g_cnt_l0[it][bx], 1);

    } else {
        const int lay = phase;                        // 1 or 2
        // ---- step 1: hh GEMM on prev-iter h (ready now) ----
        const half* ap_hh = h0p + (size_t)lay * SDH + (size_t)(bm + r0) * 256 + sg * 8;
        const half* wp_hh = g_w_hh[lay] + (size_t)(bn + r0) * 256 + sg * 8;
        gemm256(ap_hh, wp_hh, sbase, so0, frag, acc);

        // ---- step 2: wait for producer layer ----
        if (tid == 0) {
            volatile int* cnt = (lay == 1) ? &g_cnt_l0[it][bx] : &g_cnt_l1[it][bx];
            while (*cnt < 8) { __nanosleep(64); }
            __threadfence();
        }
        __syncthreads();

        // ---- step 3: ih GEMM on freshly-written h ----
        const half* ap_ih = hnew + (size_t)(lay - 1) * SDH + (size_t)(bm + r0) * 256 + sg * 8;
        const half* wp_ih = g_w_ih[lay] + (size_t)(bn + r0) * 256 + sg * 8;
        gemm256(ap_ih, wp_ih, sbase, so0, frag, acc);

        lstm_epilogue(acc, lane, wid, bm, bn, g_bp + lay * NGATE,
                      c + (size_t)lay * M_PAD * DIM,
                      hnew + (size_t)lay * SDH, hq, (lay == 2) ? 1 : 0);
        if (lay == 1) {
            __threadfence();
            __syncthreads();
            if (tid == 0) atomicAdd(&g_cnt_l1[it][bx], 1);
        }
    }
}

// ---------------- fused attention (fp16 feats) -----------------------------------
__global__ void attn_kernel(const float* __restrict__ q, float* __restrict__ out) {
    const int s = blockIdx.x;
    const int lo = g_start[s], hi = g_start[s + 1];
    const int w = threadIdx.x >> 5;
    const int lane = threadIdx.x & 31;

    __shared__ float sm_m[8];
    __shared__ float sm_s[8];
    __shared__ float sm_r[8][256];

    float qf[8];
    *(float4*)&qf[0] = *(const float4*)(q + (size_t)s * DIM + lane * 8);
    *(float4*)&qf[4] = *(const float4*)(q + (size_t)s * DIM + lane * 8 + 4);

    float m = -INFINITY, ssum = 0.0f;
    float r[8];
#pragma unroll
    for (int j = 0; j < 8; j++) r[j] = 0.0f;

    for (int n = lo + w; n < hi; n += 8) {
        uint4 fv = *(const uint4*)(g_featsh + (size_t)n * DIM + lane * 8);
        float2 f0 = __half22float2(*(half2*)&fv.x);
        float2 f1 = __half22float2(*(half2*)&fv.y);
        float2 f2 = __half22float2(*(half2*)&fv.z);
        float2 f3 = __half22float2(*(half2*)&fv.w);
        float ff[8] = {f0.x, f0.y, f1.x, f1.y, f2.x, f2.y, f3.x, f3.y};
        float d = 0.0f;
#pragma unroll
        for (int j = 0; j < 8; j++) d = fmaf(ff[j], qf[j], d);
#pragma unroll
        for (int o = 16; o > 0; o >>= 1) d += __shfl_xor_sync(0xffffffffu, d, o);

        float mn = fmaxf(m, d);
        float sc = __expf(m - mn);
        float p  = __expf(d - mn);
        ssum = ssum * sc + p;
#pragma unroll
        for (int j = 0; j < 8; j++) r[j] = r[j] * sc + p * ff[j];
        m = mn;
    }

    if (lane == 0) { sm_m[w] = m; sm_s[w] = ssum; }
    *(float4*)&sm_r[w][lane * 8]     = *(float4*)&r[0];
    *(float4*)&sm_r[w][lane * 8 + 4] = *(float4*)&r[4];
    __syncthreads();

    const int t = threadIdx.x;
    float M = -INFINITY;
#pragma unroll
    for (int k = 0; k < 8; k++)
        if (sm_s[k] > 0.0f) M = fmaxf(M, sm_m[k]);
    float S = 0.0f, R = 0.0f;
#pragma unroll
    for (int k = 0; k < 8; k++) {
        if (sm_s[k] > 0.0f) {
            float sc = __expf(sm_m[k] - M);
            S += sm_s[k] * sc;
            R += sm_r[k][t] * sc;
        }
    }
    float rv = (S > 0.0f) ? R / S : 0.0f;
    float qv_ = q[(size_t)s * DIM + t];
    out[(size_t)s * QSTAR + t]       = qv_;
    out[(size_t)s * QSTAR + DIM + t] = rv;

    half* qs = g_qstar + (size_t)s * 512;
    qs[t]       = __float2half_rn(qv_);
    qs[256 + t] = __float2half_rn(rv);
}

// ---------------- host orchestration -------------------------------------------
extern "C" void kernel_launch(void* const* d_in, const int* in_sizes, int n_in,
                              void* d_out, int out_size) {
    const float* feats = (const float*)d_in[0];
    const int* seg = (const int*)d_in[1];
    float* out = (float*)d_out;

    PermArgs pa;
    for (int l = 0; l < 3; l++) {
        pa.w_ih[l] = (const float*)d_in[2 + 4 * l];
        pa.w_hh[l] = (const float*)d_in[3 + 4 * l];
        pa.b_ih[l] = (const float*)d_in[4 + 4 * l];
        pa.b_hh[l] = (const float*)d_in[5 + 4 * l];
        pa.K1[l] = (l == 0) ? QSTAR : DIM;
    }

    half *qs, *hh; float *c, *hq;
    cudaGetSymbolAddress((void**)&qs, g_qstar);
    cudaGetSymbolAddress((void**)&hh, g_hh);
    cudaGetSymbolAddress((void**)&c, g_c);
    cudaGetSymbolAddress((void**)&hq, g_hq);

    cudaFuncSetAttribute(gemm_all, cudaFuncAttributeMaxDynamicSharedMemorySize, SMEM_GE);

    dim3 pgrid(256, 3);
    prep_kernel<<<pgrid, 256>>>(pa);
    feats_conv_kernel<<<2048, 256>>>(feats);
    init_kernel<<<1184, 256>>>(seg);

    const size_t SDH = (size_t)M_PAD * 256;

    for (int it = 0; it < NITER; it++) {
        half* hin  = hh + (size_t)(it & 1) * 3 * SDH;
        half* hout = hh + (size_t)((it + 1) & 1) * 3 * SDH;
        gemm_all<<<1896, 256, SMEM_GE>>>(qs, hin, hout, c, hq, it);
        attn_kernel<<<N_SEG, 256>>>(hq, out);
    }
}